// round 13
// baseline (speedup 1.0000x reference)
#include <cuda_runtime.h>
#include <cuda_fp16.h>
#include <math.h>
#include <stdint.h>

// ---------------------------------------------------------------------------
// Problem constants
// ---------------------------------------------------------------------------
#define B_SZ 4
#define L_SZ 2048
#define G_SZ 2
#define D_SZ 2048
#define H_SZ 16
#define DE_SZ 64
#define E_SZ 1024
#define N_SZ 32768
#define ROWS (B_SZ * L_SZ)  // 8192
#define CD (G_SZ * D_SZ)    // 4096
#define NTOT 6144
#define PAD 9
#define OUT_ELEMS ((size_t)ROWS * CD)
#define EPS_DEF 1.1920928955078125e-7f
#define EPS_SC 1e-5f

#define TILE_M 128
#define TILE_N 128
#define BK 32
#define NITER (E_SZ / BK)      // 32
#define STAGE_BYTES 16384      // A 8K | W 8K
#define NSTAGE 4
#define SMEM_TOTAL (NSTAGE * STAGE_BYTES) // 65536
#define NBLK_K 32
#define NBLK_V 16
#define NTILES ((NTOT / TILE_N) * (ROWS / TILE_M)) // 3072
#define GEMM_CTAS 304
#define CONVW_BLOCKS ((NTOT * E_SZ / 4) / 256) // 6144

#define LCH 16                 // rows per conv thread (2048/16 = 128 exact)
#define NCHUNK (L_SZ / LCH)    // 128

// ---------------------------------------------------------------------------
// Scratch
// ---------------------------------------------------------------------------
__device__ __half g_ea[(size_t)ROWS * E_SZ];
__device__ __half g_wh[(size_t)NTOT * E_SZ];
__device__ float  g_vpb[(size_t)ROWS * D_SZ];
__device__ float  g_partK[3 * NBLK_K * (size_t)ROWS]; // [m][blk][row]
__device__ float  g_partV[NBLK_V * (size_t)ROWS];     // [blk][row]
__device__ float4 g_rs[ROWS];                         // {gate0, gate1, q0, q1}

// ---------------------------------------------------------------------------
// PTX helpers
// ---------------------------------------------------------------------------
__device__ __forceinline__ uint32_t smem_to_u32(const void* p) {
    uint32_t a;
    asm("{ .reg .u64 t; cvta.to.shared.u64 t, %1; cvt.u32.u64 %0, t; }"
        : "=r"(a) : "l"(p));
    return a;
}
__device__ __forceinline__ void cpasync16(uint32_t s, const void* g) {
    asm volatile("cp.async.cg.shared.global [%0], [%1], 16;" :: "r"(s), "l"(g));
}
#define CP_COMMIT() asm volatile("cp.async.commit_group;" ::: "memory")
#define CP_WAIT(n)  asm volatile("cp.async.wait_group %0;" :: "n"(n) : "memory")

__device__ __forceinline__ void ldsm4(uint32_t* r, uint32_t a) {
    asm volatile("ldmatrix.sync.aligned.m8n8.x4.shared.b16 {%0,%1,%2,%3}, [%4];"
        : "=r"(r[0]), "=r"(r[1]), "=r"(r[2]), "=r"(r[3]) : "r"(a));
}
__device__ __forceinline__ void mma16816(float* c, const uint32_t* a, const uint32_t* b) {
    asm volatile(
        "mma.sync.aligned.m16n8k16.row.col.f32.f16.f16.f32 "
        "{%0,%1,%2,%3}, {%4,%5,%6,%7}, {%8,%9}, {%0,%1,%2,%3};"
        : "+f"(c[0]), "+f"(c[1]), "+f"(c[2]), "+f"(c[3])
        : "r"(a[0]), "r"(a[1]), "r"(a[2]), "r"(a[3]), "r"(b[0]), "r"(b[1]));
}
__device__ __forceinline__ uint32_t sw32(uint32_t o) { return o ^ ((o >> 3) & 0x10); }

__device__ __forceinline__ float silu_fast(float a) {
    return __fdividef(a, 1.f + __expf(-a));
}

// ---------------------------------------------------------------------------
// 1) prep: gather emb->fp16 + convert W->fp16
// ---------------------------------------------------------------------------
__global__ void __launch_bounds__(256) prep(
    const int* __restrict__ ids, const float* __restrict__ table,
    const float* __restrict__ Wk, const float* __restrict__ Wv)
{
    int blk = blockIdx.x;
    int t = threadIdx.x;
    if (blk < ROWS) {
        int r = blk;
        const int* idr = ids + r * H_SZ;
        int e  = t * 4;
        int h  = e >> 6;
        int de = e & 63;
        int id = idr[h];
        float4 v = *(const float4*)&table[((size_t)(h * N_SZ + id)) * DE_SZ + de];
        __half2 p0, p1;
        p0.x = __float2half_rn(v.x); p0.y = __float2half_rn(v.y);
        p1.x = __float2half_rn(v.z); p1.y = __float2half_rn(v.w);
        *(__half2*)&g_ea[(size_t)r * E_SZ + e]     = p0;
        *(__half2*)&g_ea[(size_t)r * E_SZ + e + 2] = p1;
    } else {
        size_t idx = ((size_t)(blk - ROWS) * 256 + t) * 4;
        size_t n = idx >> 10;
        const float* src = (n < 4096) ? (Wk + idx)
                                      : (Wv + (idx - (size_t)4096 * E_SZ));
        float4 v = *(const float4*)src;
        __half2 h0, h1;
        h0.x = __float2half_rn(v.x); h0.y = __float2half_rn(v.y);
        h1.x = __float2half_rn(v.z); h1.y = __float2half_rn(v.w);
        *(__half2*)&g_wh[idx]     = h0;
        *(__half2*)&g_wh[idx + 2] = h1;
    }
}

// ---------------------------------------------------------------------------
// 2) Merged fp16 GEMM, persistent CTAs over 3072 tiles, 2 CTAs/SM
// ---------------------------------------------------------------------------
__global__ void __launch_bounds__(256, 2) gemm_fused(
    const float* __restrict__ bk, const float* __restrict__ bv,
    const float* __restrict__ hid,
    const float* __restrict__ n1w, const float* __restrict__ n2w)
{
    extern __shared__ __align__(1024) char smem[];
    const uint32_t sbase = smem_to_u32(smem);
    const int tid = threadIdx.x, wid = tid >> 5, lane = tid & 31;
    const int wm = wid & 1, wn = wid >> 1;
    const int gq = lane >> 2, tg = lane & 3;

    const uint32_t offA = sw32((uint32_t)((wm * 64 + (lane & 15)) * 32 + (lane >> 4) * 16));
    const uint32_t offB = sw32((uint32_t)((wn * 32 + ((lane >> 4) << 3) + (lane & 7)) * 32 +
                                          ((lane >> 3) & 1) * 16));

    for (int tile = blockIdx.x; tile < NTILES; tile += GEMM_CTAS) {
        const int bx = tile % (NTOT / TILE_N);   // 0..47
        const int m0 = (tile / (NTOT / TILE_N)) * TILE_M;
        const int n0w = bx * TILE_N;

        auto fill = [&](int kt, int s) {
            const uint32_t st = sbase + (uint32_t)s * STAGE_BYTES;
            const int kb = kt * BK;
#pragma unroll
            for (int i = 0; i < 4; ++i) {
                int u = tid + i * 256;
                int isW = (u >= 512);
                int v = u & 511;
                int r = v >> 2, q = v & 3;
                uint32_t a = st + isW * 8192 + (q >> 1) * 4096 +
                             sw32((uint32_t)(r * 32 + (q & 1) * 16));
                const __half* gp = isW ? (g_wh + (size_t)(n0w + r) * E_SZ + kb + q * 8)
                                       : (g_ea + (size_t)(m0 + r) * E_SZ + kb + q * 8);
                cpasync16(a, gp);
            }
        };

        float acc[4][4][4];
#pragma unroll
        for (int mi = 0; mi < 4; ++mi)
#pragma unroll
            for (int ni = 0; ni < 4; ++ni)
#pragma unroll
                for (int j = 0; j < 4; ++j) acc[mi][ni][j] = 0.f;

        fill(0, 0); CP_COMMIT();
        fill(1, 1); CP_COMMIT();
        fill(2, 2); CP_COMMIT();

        for (int it = 0; it < NITER; ++it) {
            CP_WAIT(2);
            __syncthreads();
            if (it + 3 < NITER) fill(it + 3, (it + 3) % NSTAGE);
            CP_COMMIT();   // unconditional: keeps wait_group(2) == stage ready

            const uint32_t st = sbase + (uint32_t)(it % NSTAGE) * STAGE_BYTES;
#pragma unroll
            for (int ch = 0; ch < 2; ++ch) {
                const uint32_t aA = st + ch * 4096 + offA;
                const uint32_t bW = st + 8192 + ch * 4096 + offB;
                uint32_t av[4][4], bw[4][2];
#pragma unroll
                for (int mi = 0; mi < 4; ++mi)
                    ldsm4(av[mi], aA + (uint32_t)(mi * 16 * 32));
#pragma unroll
                for (int np = 0; np < 2; ++np) {
                    uint32_t r4[4];
                    ldsm4(r4, bW + (uint32_t)(np * 16 * 32));
                    bw[2 * np][0] = r4[0]; bw[2 * np][1] = r4[1];
                    bw[2 * np + 1][0] = r4[2]; bw[2 * np + 1][1] = r4[3];
                }
#pragma unroll
                for (int mi = 0; mi < 4; ++mi)
#pragma unroll
                    for (int ni = 0; ni < 4; ++ni)
                        mma16816(acc[mi][ni], av[mi], bw[ni]);
            }
            __syncthreads();
        }

        if (bx < NBLK_K) {
            // ---- keyp epilogue: reduce {ssk, cr, ssq} ----
            const int n0 = bx * TILE_N;
            float* w12s = (float*)smem;
            float* bks  = (float*)(smem) + 128;
            float* sred = (float*)(smem) + 256;
            if (tid < 128) {
                w12s[tid] = n1w[n0 + tid] * n2w[n0 + tid];
                bks[tid]  = bk[n0 + tid];
            }
            __syncthreads();

            float pssk[8], pcr[8], pssq[8];
#pragma unroll
            for (int i = 0; i < 8; ++i) { pssk[i] = 0.f; pcr[i] = 0.f; pssq[i] = 0.f; }

#pragma unroll
            for (int mi = 0; mi < 4; ++mi) {
#pragma unroll
                for (int half = 0; half < 2; ++half) {
                    int row = m0 + wm * 64 + mi * 16 + gq + half * 8;
                    const float* hrow = hid + (size_t)row * CD + n0;
                    int s8 = mi * 2 + half;
#pragma unroll
                    for (int ni = 0; ni < 4; ++ni) {
                        int cl = wn * 32 + ni * 8 + tg * 2;
                        float2 h = *(const float2*)&hrow[cl];
                        float k0 = acc[mi][ni][half * 2 + 0] + bks[cl];
                        float k1 = acc[mi][ni][half * 2 + 1] + bks[cl + 1];
                        pssk[s8] += k0 * k0 + k1 * k1;
                        pcr[s8]  += k0 * h.x * w12s[cl] + k1 * h.y * w12s[cl + 1];
                        pssq[s8] += h.x * h.x + h.y * h.y;
                    }
                }
            }
#pragma unroll
            for (int i = 0; i < 8; ++i) {
                pssk[i] += __shfl_xor_sync(0xffffffffu, pssk[i], 1);
                pssk[i] += __shfl_xor_sync(0xffffffffu, pssk[i], 2);
                pcr[i]  += __shfl_xor_sync(0xffffffffu, pcr[i], 1);
                pcr[i]  += __shfl_xor_sync(0xffffffffu, pcr[i], 2);
                pssq[i] += __shfl_xor_sync(0xffffffffu, pssq[i], 1);
                pssq[i] += __shfl_xor_sync(0xffffffffu, pssq[i], 2);
            }
            if (tg == 0) {
#pragma unroll
                for (int mi = 0; mi < 4; ++mi)
#pragma unroll
                    for (int half = 0; half < 2; ++half) {
                        int rl = wm * 64 + mi * 16 + gq + half * 8;
                        int s8 = mi * 2 + half;
                        sred[0 * 512 + rl * 4 + wn] = pssk[s8];
                        sred[1 * 512 + rl * 4 + wn] = pcr[s8];
                        sred[2 * 512 + rl * 4 + wn] = pssq[s8];
                    }
            }
            __syncthreads();
            if (tid < 128) {
#pragma unroll
                for (int m = 0; m < 3; ++m) {
                    float s = sred[m * 512 + tid * 4 + 0] + sred[m * 512 + tid * 4 + 1] +
                              sred[m * 512 + tid * 4 + 2] + sred[m * 512 + tid * 4 + 3];
                    g_partK[((size_t)m * NBLK_K + bx) * ROWS + m0 + tid] = s;
                }
            }
        } else {
            // ---- vproj epilogue: store vpb + reduce sv ----
            const int c0 = (bx - NBLK_K) * TILE_N;
            float* bvs  = (float*)smem;
            float* sred = (float*)(smem) + 128;
            if (tid < 128) bvs[tid] = bv[c0 + tid];
            __syncthreads();

            float psv[8];
#pragma unroll
            for (int i = 0; i < 8; ++i) psv[i] = 0.f;

#pragma unroll
            for (int mi = 0; mi < 4; ++mi) {
#pragma unroll
                for (int half = 0; half < 2; ++half) {
                    int row = m0 + wm * 64 + mi * 16 + gq + half * 8;
                    int s8 = mi * 2 + half;
                    float* vrow = g_vpb + (size_t)row * D_SZ + c0;
#pragma unroll
                    for (int ni = 0; ni < 4; ++ni) {
                        int cl = wn * 32 + ni * 8 + tg * 2;
                        float v0 = acc[mi][ni][half * 2 + 0] + bvs[cl];
                        float v1 = acc[mi][ni][half * 2 + 1] + bvs[cl + 1];
                        psv[s8] += v0 * v0 + v1 * v1;
                        float2 o; o.x = v0; o.y = v1;
                        *(float2*)&vrow[cl] = o;
                    }
                }
            }
#pragma unroll
            for (int i = 0; i < 8; ++i) {
                psv[i] += __shfl_xor_sync(0xffffffffu, psv[i], 1);
                psv[i] += __shfl_xor_sync(0xffffffffu, psv[i], 2);
            }
            if (tg == 0) {
#pragma unroll
                for (int mi = 0; mi < 4; ++mi)
#pragma unroll
                    for (int half = 0; half < 2; ++half) {
                        int rl = wm * 64 + mi * 16 + gq + half * 8;
                        sred[rl * 4 + wn] = psv[mi * 2 + half];
                    }
            }
            __syncthreads();
            if (tid < 128) {
                float s = sred[tid * 4 + 0] + sred[tid * 4 + 1] +
                          sred[tid * 4 + 2] + sred[tid * 4 + 3];
                g_partV[(size_t)(bx - NBLK_K) * ROWS + m0 + tid] = s;
            }
        }
        __syncthreads();   // smem reuse barrier before next tile's fills
    }
}

// ---------------------------------------------------------------------------
// 3) rowstats
// ---------------------------------------------------------------------------
__global__ void __launch_bounds__(256) rowstats()
{
    int r = blockIdx.x * 256 + threadIdx.x;
    float ssk[2] = {0.f, 0.f}, cr[2] = {0.f, 0.f}, ssq[2] = {0.f, 0.f};
#pragma unroll
    for (int bx = 0; bx < NBLK_K; ++bx) {
        int gg = bx >> 4;
        ssk[gg] += g_partK[((size_t)0 * NBLK_K + bx) * ROWS + r];
        cr[gg]  += g_partK[((size_t)1 * NBLK_K + bx) * ROWS + r];
        ssq[gg] += g_partK[((size_t)2 * NBLK_K + bx) * ROWS + r];
    }
    float sv = 0.f;
#pragma unroll
    for (int bx = 0; bx < NBLK_V; ++bx)
        sv += g_partV[(size_t)bx * ROWS + r];

    const float invD = 1.0f / 2048.0f;
    const float invSqrtD = 0.022097086912079610f;
    float4 rs;
    float gate[2], q[2];
#pragma unroll
    for (int gg = 0; gg < 2; ++gg) {
        float rsk = rsqrtf(ssk[gg] * invD + EPS_DEF);
        float rsq = rsqrtf(ssq[gg] * invD + EPS_DEF);
        float gt  = rsk * rsq * cr[gg] * invSqrtD;
        float sg  = (gt > 0.f) ? 1.f : ((gt < 0.f) ? -1.f : 0.f);
        float sq  = sqrtf(fmaxf(fabsf(gt), 1e-6f)) * sg;
        gate[gg] = __fdividef(1.f, 1.f + __expf(-sq));
        float inv = rsqrtf(gate[gg] * gate[gg] * sv * invD + EPS_SC);
        q[gg] = gate[gg] * inv;
    }
    rs.x = gate[0]; rs.y = gate[1]; rs.z = q[0]; rs.w = q[1];
    g_rs[r] = rs;
}

// ---------------------------------------------------------------------------
// 4) conv_out: 16 rows per thread, 2 channels, static rolling window
// ---------------------------------------------------------------------------
__global__ void __launch_bounds__(256) conv_out(
    const float* __restrict__ cw, const float* __restrict__ scw,
    float* __restrict__ out)
{
    int t = blockIdx.x * blockDim.x + threadIdx.x;
    int c2 = t & 2047;            // CD/2 groups
    int chunk = t >> 11;          // 0 .. 4*128-1
    int b = chunk >> 7;
    int l0 = (chunk & 127) << 4;

    int c = c2 << 1;
    int gg = c >> 11;
    int d  = c & (D_SZ - 1);
    int r0 = b * L_SZ + l0;

    float4 w0 = *(const float4*)(cw + (size_t)c * 4);
    float4 w1 = *(const float4*)(cw + (size_t)(c + 1) * 4);
    float2 sc = *(const float2*)(scw + c);

    float2 win[LCH];
    if (l0 != 0) {
        const float* vp = g_vpb + (size_t)(r0 - 9) * D_SZ + d;
        const float4* rp = g_rs + (r0 - 9);
#pragma unroll
        for (int j = 9; j >= 1; --j) {    // rows r0-9 .. r0-1, slots 7..15
            float2 vv = *(const float2*)vp;
            float4 rr = *rp;
            float q = gg ? rr.w : rr.z;
            float2 x;
            x.x = vv.x * q * sc.x; x.y = vv.y * q * sc.y;
            win[LCH - j] = x;
            vp += D_SZ; ++rp;
        }
    } else {
#pragma unroll
        for (int j = 1; j <= 9; ++j)
            win[LCH - j] = make_float2(0.f, 0.f);
    }

    const float* vp = g_vpb + (size_t)r0 * D_SZ + d;
    const float4* rp = g_rs + r0;
    float* op = out + (size_t)r0 * CD + c;

#pragma unroll
    for (int i = 0; i < LCH; ++i) {
        float2 vo = *(const float2*)vp;
        float4 rr = *rp;
        float gate = gg ? rr.y : rr.x;
        float q    = gg ? rr.w : rr.z;
        float2 x;
        x.x = vo.x * q * sc.x; x.y = vo.y * q * sc.y;
        win[i] = x;

        float a0 = w0.w * x.x, a1 = w1.w * x.y;
        float2 t3 = win[(i + 13) & 15];   // l-3
        a0 += w0.z * t3.x; a1 += w1.z * t3.y;
        float2 t6 = win[(i + 10) & 15];   // l-6
        a0 += w0.y * t6.x; a1 += w1.y * t6.y;
        float2 t9 = win[(i + 7) & 15];    // l-9
        a0 += w0.x * t9.x; a1 += w1.x * t9.y;

        float2 o;
        o.x = gate * vo.x + silu_fast(a0);
        o.y = gate * vo.y + silu_fast(a1);
        *(float2*)op = o;

        vp += D_SZ; ++rp; op += CD;
    }

    // cache tail: last chunk holds l = 2039..2047 in win slots 7..15
    if (l0 == L_SZ - LCH) {
        size_t cbase = OUT_ELEMS + (size_t)b * CD * PAD;
#pragma unroll
        for (int j = 0; j < PAD; ++j) {   // l = 2039+j, slot = 7+j
            float2 x = win[7 + j];
            out[cbase + (size_t)(c + 0) * PAD + j] = x.x;
            out[cbase + (size_t)(c + 1) * PAD + j] = x.y;
        }
    }
}

// ---------------------------------------------------------------------------
// launch
// ---------------------------------------------------------------------------
extern "C" void kernel_launch(void* const* d_in, const int* in_sizes, int n_in,
                              void* d_out, int out_size)
{
    const float* hid   = (const float*)d_in[0];
    const int*   ids   = (const int*)  d_in[1];
    const float* table = (const float*)d_in[2];
    const float* Wk    = (const float*)d_in[3];
    const float* bk    = (const float*)d_in[4];
    const float* Wv    = (const float*)d_in[5];
    const float* bv    = (const float*)d_in[6];
    const float* n1    = (const float*)d_in[7];
    const float* n2    = (const float*)d_in[8];
    const float* cw    = (const float*)d_in[9];
    const float* scw   = (const float*)d_in[10];
    float* out = (float*)d_out;

    cudaFuncSetAttribute(gemm_fused, cudaFuncAttributeMaxDynamicSharedMemorySize,
                         SMEM_TOTAL);

    prep<<<ROWS + CONVW_BLOCKS, 256>>>(ids, table, Wk, Wv);
    gemm_fused<<<GEMM_CTAS, 256, SMEM_TOTAL>>>(bk, bv, hid, n1, n2);
    rowstats<<<ROWS / 256, 256>>>();
    int conv_threads = 2048 * B_SZ * NCHUNK;   // 2048 * 512
    conv_out<<<conv_threads / 256, 256>>>(cw, scw, out);
}

// round 15
// speedup vs baseline: 1.0019x; 1.0019x over previous
#include <cuda_runtime.h>
#include <cuda_fp16.h>
#include <math.h>
#include <stdint.h>

// ---------------------------------------------------------------------------
// Problem constants
// ---------------------------------------------------------------------------
#define B_SZ 4
#define L_SZ 2048
#define G_SZ 2
#define D_SZ 2048
#define H_SZ 16
#define DE_SZ 64
#define E_SZ 1024
#define N_SZ 32768
#define ROWS (B_SZ * L_SZ)  // 8192
#define CD (G_SZ * D_SZ)    // 4096
#define NTOT 6144
#define PAD 9
#define OUT_ELEMS ((size_t)ROWS * CD)
#define EPS_DEF 1.1920928955078125e-7f
#define EPS_SC 1e-5f

#define TILE_M 128
#define TILE_N 128
#define BK 32
#define NITER (E_SZ / BK)      // 32
#define STAGE_BYTES 16384      // A 8K | W 8K
#define NSTAGE 4
#define SMEM_TOTAL (NSTAGE * STAGE_BYTES) // 65536
#define NBLK_K 32
#define NBLK_V 16
#define CONVW_BLOCKS ((NTOT * E_SZ / 4) / 256) // 6144

#define LCH 8                  // rows per conv thread (2048/8 = 256 exact)
#define NCHUNK (L_SZ / LCH)    // 256

// ---------------------------------------------------------------------------
// Scratch
// ---------------------------------------------------------------------------
__device__ __half g_ea[(size_t)ROWS * E_SZ];
__device__ __half g_wh[(size_t)NTOT * E_SZ];
__device__ float  g_vpb[(size_t)ROWS * D_SZ];
__device__ float  g_partK[3 * NBLK_K * (size_t)ROWS]; // [m][blk][row]
__device__ float  g_partV[NBLK_V * (size_t)ROWS];     // [blk][row]
__device__ float4 g_rs[ROWS];                         // {gate0, gate1, q0, q1}

// ---------------------------------------------------------------------------
// PTX helpers
// ---------------------------------------------------------------------------
__device__ __forceinline__ uint32_t smem_to_u32(const void* p) {
    uint32_t a;
    asm("{ .reg .u64 t; cvta.to.shared.u64 t, %1; cvt.u32.u64 %0, t; }"
        : "=r"(a) : "l"(p));
    return a;
}
__device__ __forceinline__ void cpasync16(uint32_t s, const void* g) {
    asm volatile("cp.async.cg.shared.global [%0], [%1], 16;" :: "r"(s), "l"(g));
}
#define CP_COMMIT() asm volatile("cp.async.commit_group;" ::: "memory")
#define CP_WAIT(n)  asm volatile("cp.async.wait_group %0;" :: "n"(n) : "memory")

__device__ __forceinline__ void ldsm4(uint32_t* r, uint32_t a) {
    asm volatile("ldmatrix.sync.aligned.m8n8.x4.shared.b16 {%0,%1,%2,%3}, [%4];"
        : "=r"(r[0]), "=r"(r[1]), "=r"(r[2]), "=r"(r[3]) : "r"(a));
}
__device__ __forceinline__ void mma16816(float* c, const uint32_t* a, const uint32_t* b) {
    asm volatile(
        "mma.sync.aligned.m16n8k16.row.col.f32.f16.f16.f32 "
        "{%0,%1,%2,%3}, {%4,%5,%6,%7}, {%8,%9}, {%0,%1,%2,%3};"
        : "+f"(c[0]), "+f"(c[1]), "+f"(c[2]), "+f"(c[3])
        : "r"(a[0]), "r"(a[1]), "r"(a[2]), "r"(a[3]), "r"(b[0]), "r"(b[1]));
}
__device__ __forceinline__ uint32_t sw32(uint32_t o) { return o ^ ((o >> 3) & 0x10); }

__device__ __forceinline__ float silu_fast(float a) {
    return __fdividef(a, 1.f + __expf(-a));
}

// ---------------------------------------------------------------------------
// 1) prep: gather emb->fp16 + convert W->fp16
// ---------------------------------------------------------------------------
__global__ void __launch_bounds__(256) prep(
    const int* __restrict__ ids, const float* __restrict__ table,
    const float* __restrict__ Wk, const float* __restrict__ Wv)
{
    int blk = blockIdx.x;
    int t = threadIdx.x;
    if (blk < ROWS) {
        int r = blk;
        const int* idr = ids + r * H_SZ;
        int e  = t * 4;
        int h  = e >> 6;
        int de = e & 63;
        int id = idr[h];
        float4 v = *(const float4*)&table[((size_t)(h * N_SZ + id)) * DE_SZ + de];
        __half2 p0, p1;
        p0.x = __float2half_rn(v.x); p0.y = __float2half_rn(v.y);
        p1.x = __float2half_rn(v.z); p1.y = __float2half_rn(v.w);
        *(__half2*)&g_ea[(size_t)r * E_SZ + e]     = p0;
        *(__half2*)&g_ea[(size_t)r * E_SZ + e + 2] = p1;
    } else {
        size_t idx = ((size_t)(blk - ROWS) * 256 + t) * 4;
        size_t n = idx >> 10;
        const float* src = (n < 4096) ? (Wk + idx)
                                      : (Wv + (idx - (size_t)4096 * E_SZ));
        float4 v = *(const float4*)src;
        __half2 h0, h1;
        h0.x = __float2half_rn(v.x); h0.y = __float2half_rn(v.y);
        h1.x = __float2half_rn(v.z); h1.y = __float2half_rn(v.w);
        *(__half2*)&g_wh[idx]     = h0;
        *(__half2*)&g_wh[idx + 2] = h1;
    }
}

// ---------------------------------------------------------------------------
// 2) Merged fp16 GEMM, 128x128 tiles, 2 CTAs/SM (per-tile grid)
// ---------------------------------------------------------------------------
__global__ void __launch_bounds__(256, 2) gemm_fused(
    const float* __restrict__ bk, const float* __restrict__ bv,
    const float* __restrict__ hid,
    const float* __restrict__ n1w, const float* __restrict__ n2w)
{
    extern __shared__ __align__(1024) char smem[];
    const uint32_t sbase = smem_to_u32(smem);
    const int tid = threadIdx.x, wid = tid >> 5, lane = tid & 31;
    const int bx = blockIdx.x;
    const int m0 = blockIdx.y * TILE_M;
    const int n0w = bx * TILE_N;
    const int wm = wid & 1, wn = wid >> 1;

    auto fill = [&](int kt, int s) {
        const uint32_t st = sbase + (uint32_t)s * STAGE_BYTES;
        const int kb = kt * BK;
#pragma unroll
        for (int i = 0; i < 4; ++i) {
            int u = tid + i * 256;
            int isW = (u >= 512);
            int v = u & 511;
            int r = v >> 2, q = v & 3;
            uint32_t a = st + isW * 8192 + (q >> 1) * 4096 +
                         sw32((uint32_t)(r * 32 + (q & 1) * 16));
            const __half* gp = isW ? (g_wh + (size_t)(n0w + r) * E_SZ + kb + q * 8)
                                   : (g_ea + (size_t)(m0 + r) * E_SZ + kb + q * 8);
            cpasync16(a, gp);
        }
    };

    float acc[4][4][4];
#pragma unroll
    for (int mi = 0; mi < 4; ++mi)
#pragma unroll
        for (int ni = 0; ni < 4; ++ni)
#pragma unroll
            for (int j = 0; j < 4; ++j) acc[mi][ni][j] = 0.f;

    fill(0, 0); CP_COMMIT();
    fill(1, 1); CP_COMMIT();
    fill(2, 2); CP_COMMIT();

    const uint32_t offA = sw32((uint32_t)((wm * 64 + (lane & 15)) * 32 + (lane >> 4) * 16));
    const uint32_t offB = sw32((uint32_t)((wn * 32 + ((lane >> 4) << 3) + (lane & 7)) * 32 +
                                          ((lane >> 3) & 1) * 16));

    for (int it = 0; it < NITER; ++it) {
        CP_WAIT(2);
        __syncthreads();
        if (it + 3 < NITER) fill(it + 3, (it + 3) % NSTAGE);
        CP_COMMIT();   // unconditional: keeps wait_group(2) == stage resident

        const uint32_t st = sbase + (uint32_t)(it % NSTAGE) * STAGE_BYTES;
#pragma unroll
        for (int ch = 0; ch < 2; ++ch) {
            const uint32_t aA = st + ch * 4096 + offA;
            const uint32_t bW = st + 8192 + ch * 4096 + offB;
            uint32_t av[4][4], bw[4][2];
#pragma unroll
            for (int mi = 0; mi < 4; ++mi)
                ldsm4(av[mi], aA + (uint32_t)(mi * 16 * 32));
#pragma unroll
            for (int np = 0; np < 2; ++np) {
                uint32_t r4[4];
                ldsm4(r4, bW + (uint32_t)(np * 16 * 32));
                bw[2 * np][0] = r4[0]; bw[2 * np][1] = r4[1];
                bw[2 * np + 1][0] = r4[2]; bw[2 * np + 1][1] = r4[3];
            }
#pragma unroll
            for (int mi = 0; mi < 4; ++mi)
#pragma unroll
                for (int ni = 0; ni < 4; ++ni)
                    mma16816(acc[mi][ni], av[mi], bw[ni]);
        }
        __syncthreads();
    }

    const int gq = lane >> 2, tg = lane & 3;

    if (bx < NBLK_K) {
        const int n0 = bx * TILE_N;
        float* w12s = (float*)smem;
        float* bks  = (float*)(smem) + 128;
        float* sred = (float*)(smem) + 256;
        if (tid < 128) {
            w12s[tid] = n1w[n0 + tid] * n2w[n0 + tid];
            bks[tid]  = bk[n0 + tid];
        }
        __syncthreads();

        float pssk[8], pcr[8], pssq[8];
#pragma unroll
        for (int i = 0; i < 8; ++i) { pssk[i] = 0.f; pcr[i] = 0.f; pssq[i] = 0.f; }

#pragma unroll
        for (int mi = 0; mi < 4; ++mi) {
#pragma unroll
            for (int half = 0; half < 2; ++half) {
                int row = m0 + wm * 64 + mi * 16 + gq + half * 8;
                const float* hrow = hid + (size_t)row * CD + n0;
                int s8 = mi * 2 + half;
#pragma unroll
                for (int ni = 0; ni < 4; ++ni) {
                    int cl = wn * 32 + ni * 8 + tg * 2;
                    float2 h = *(const float2*)&hrow[cl];
                    float k0 = acc[mi][ni][half * 2 + 0] + bks[cl];
                    float k1 = acc[mi][ni][half * 2 + 1] + bks[cl + 1];
                    pssk[s8] += k0 * k0 + k1 * k1;
                    pcr[s8]  += k0 * h.x * w12s[cl] + k1 * h.y * w12s[cl + 1];
                    pssq[s8] += h.x * h.x + h.y * h.y;
                }
            }
        }
#pragma unroll
        for (int i = 0; i < 8; ++i) {
            pssk[i] += __shfl_xor_sync(0xffffffffu, pssk[i], 1);
            pssk[i] += __shfl_xor_sync(0xffffffffu, pssk[i], 2);
            pcr[i]  += __shfl_xor_sync(0xffffffffu, pcr[i], 1);
            pcr[i]  += __shfl_xor_sync(0xffffffffu, pcr[i], 2);
            pssq[i] += __shfl_xor_sync(0xffffffffu, pssq[i], 1);
            pssq[i] += __shfl_xor_sync(0xffffffffu, pssq[i], 2);
        }
        if (tg == 0) {
#pragma unroll
            for (int mi = 0; mi < 4; ++mi)
#pragma unroll
                for (int half = 0; half < 2; ++half) {
                    int rl = wm * 64 + mi * 16 + gq + half * 8;
                    int s8 = mi * 2 + half;
                    sred[0 * 512 + rl * 4 + wn] = pssk[s8];
                    sred[1 * 512 + rl * 4 + wn] = pcr[s8];
                    sred[2 * 512 + rl * 4 + wn] = pssq[s8];
                }
        }
        __syncthreads();
        if (tid < 128) {
#pragma unroll
            for (int m = 0; m < 3; ++m) {
                float s = sred[m * 512 + tid * 4 + 0] + sred[m * 512 + tid * 4 + 1] +
                          sred[m * 512 + tid * 4 + 2] + sred[m * 512 + tid * 4 + 3];
                g_partK[((size_t)m * NBLK_K + bx) * ROWS + m0 + tid] = s;
            }
        }
    } else {
        const int c0 = (bx - NBLK_K) * TILE_N;
        float* bvs  = (float*)smem;
        float* sred = (float*)(smem) + 128;
        if (tid < 128) bvs[tid] = bv[c0 + tid];
        __syncthreads();

        float psv[8];
#pragma unroll
        for (int i = 0; i < 8; ++i) psv[i] = 0.f;

#pragma unroll
        for (int mi = 0; mi < 4; ++mi) {
#pragma unroll
            for (int half = 0; half < 2; ++half) {
                int row = m0 + wm * 64 + mi * 16 + gq + half * 8;
                int s8 = mi * 2 + half;
                float* vrow = g_vpb + (size_t)row * D_SZ + c0;
#pragma unroll
                for (int ni = 0; ni < 4; ++ni) {
                    int cl = wn * 32 + ni * 8 + tg * 2;
                    float v0 = acc[mi][ni][half * 2 + 0] + bvs[cl];
                    float v1 = acc[mi][ni][half * 2 + 1] + bvs[cl + 1];
                    psv[s8] += v0 * v0 + v1 * v1;
                    float2 o; o.x = v0; o.y = v1;
                    *(float2*)&vrow[cl] = o;
                }
            }
        }
#pragma unroll
        for (int i = 0; i < 8; ++i) {
            psv[i] += __shfl_xor_sync(0xffffffffu, psv[i], 1);
            psv[i] += __shfl_xor_sync(0xffffffffu, psv[i], 2);
        }
        if (tg == 0) {
#pragma unroll
            for (int mi = 0; mi < 4; ++mi)
#pragma unroll
                for (int half = 0; half < 2; ++half) {
                    int rl = wm * 64 + mi * 16 + gq + half * 8;
                    sred[rl * 4 + wn] = psv[mi * 2 + half];
                }
        }
        __syncthreads();
        if (tid < 128) {
            float s = sred[tid * 4 + 0] + sred[tid * 4 + 1] +
                      sred[tid * 4 + 2] + sred[tid * 4 + 3];
            g_partV[(size_t)(bx - NBLK_K) * ROWS + m0 + tid] = s;
        }
    }
}

// ---------------------------------------------------------------------------
// 3) rowstats
// ---------------------------------------------------------------------------
__global__ void __launch_bounds__(256) rowstats()
{
    int r = blockIdx.x * 256 + threadIdx.x;
    float ssk[2] = {0.f, 0.f}, cr[2] = {0.f, 0.f}, ssq[2] = {0.f, 0.f};
#pragma unroll
    for (int bx = 0; bx < NBLK_K; ++bx) {
        int gg = bx >> 4;
        ssk[gg] += g_partK[((size_t)0 * NBLK_K + bx) * ROWS + r];
        cr[gg]  += g_partK[((size_t)1 * NBLK_K + bx) * ROWS + r];
        ssq[gg] += g_partK[((size_t)2 * NBLK_K + bx) * ROWS + r];
    }
    float sv = 0.f;
#pragma unroll
    for (int bx = 0; bx < NBLK_V; ++bx)
        sv += g_partV[(size_t)bx * ROWS + r];

    const float invD = 1.0f / 2048.0f;
    const float invSqrtD = 0.022097086912079610f;
    float4 rs;
    float gate[2], q[2];
#pragma unroll
    for (int gg = 0; gg < 2; ++gg) {
        float rsk = rsqrtf(ssk[gg] * invD + EPS_DEF);
        float rsq = rsqrtf(ssq[gg] * invD + EPS_DEF);
        float gt  = rsk * rsq * cr[gg] * invSqrtD;
        float sg  = (gt > 0.f) ? 1.f : ((gt < 0.f) ? -1.f : 0.f);
        float sq  = sqrtf(fmaxf(fabsf(gt), 1e-6f)) * sg;
        gate[gg] = __fdividef(1.f, 1.f + __expf(-sq));
        float inv = rsqrtf(gate[gg] * gate[gg] * sv * invD + EPS_SC);
        q[gg] = gate[gg] * inv;
    }
    rs.x = gate[0]; rs.y = gate[1]; rs.z = q[0]; rs.w = q[1];
    g_rs[r] = rs;
}

// ---------------------------------------------------------------------------
// 4) conv_out: 8 rows per thread, 2 channels, linear 17-slot static window
//    win[0..8] = rows l0-9..l0-1 (preload, zero if row < 0),
//    win[9..16] = rows l0..l0+7.
//    Output i taps: cur=win[9+i], l-3=win[6+i], l-6=win[3+i], l-9=win[i].
// ---------------------------------------------------------------------------
__global__ void __launch_bounds__(256) conv_out(
    const float* __restrict__ cw, const float* __restrict__ scw,
    float* __restrict__ out)
{
    int t = blockIdx.x * blockDim.x + threadIdx.x;
    int c2 = t & 2047;            // CD/2 groups
    int chunk = t >> 11;          // 0 .. 4*256-1
    int b = chunk >> 8;
    int l0 = (chunk & 255) << 3;

    int c = c2 << 1;
    int gg = c >> 11;
    int d  = c & (D_SZ - 1);
    int r0 = b * L_SZ + l0;

    float4 w0 = *(const float4*)(cw + (size_t)c * 4);
    float4 w1 = *(const float4*)(cw + (size_t)(c + 1) * 4);
    float2 sc = *(const float2*)(scw + c);

    float2 win[17];
#pragma unroll
    for (int j = 0; j < 9; ++j) {        // rows l0-9+j -> win[j]; zero if l < 0
        int l = l0 - 9 + j;
        if (l >= 0) {
            int r = b * L_SZ + l;
            float2 vv = *(const float2*)(g_vpb + (size_t)r * D_SZ + d);
            float4 rr = g_rs[r];
            float q = gg ? rr.w : rr.z;
            float2 x;
            x.x = vv.x * q * sc.x; x.y = vv.y * q * sc.y;
            win[j] = x;
        } else {
            win[j] = make_float2(0.f, 0.f);
        }
    }

    const float* vp = g_vpb + (size_t)r0 * D_SZ + d;
    const float4* rp = g_rs + r0;
    float* op = out + (size_t)r0 * CD + c;

#pragma unroll
    for (int i = 0; i < LCH; ++i) {
        float2 vo = *(const float2*)vp;
        float4 rr = *rp;
        float gate = gg ? rr.y : rr.x;
        float q    = gg ? rr.w : rr.z;
        float2 x;
        x.x = vo.x * q * sc.x; x.y = vo.y * q * sc.y;
        win[9 + i] = x;

        float a0 = w0.w * x.x, a1 = w1.w * x.y;
        float2 t3 = win[6 + i];    // l-3
        a0 += w0.z * t3.x; a1 += w1.z * t3.y;
        float2 t6 = win[3 + i];    // l-6
        a0 += w0.y * t6.x; a1 += w1.y * t6.y;
        float2 t9 = win[i];        // l-9
        a0 += w0.x * t9.x; a1 += w1.x * t9.y;

        float2 o;
        o.x = gate * vo.x + silu_fast(a0);
        o.y = gate * vo.y + silu_fast(a1);
        *(float2*)op = o;

        vp += D_SZ; ++rp; op += CD;
    }

    // cache tail: last chunk (l0 = 2040) holds l = 2039..2047 in win[8..16]
    if (l0 == L_SZ - LCH) {
        size_t cbase = OUT_ELEMS + (size_t)b * CD * PAD;
#pragma unroll
        for (int j = 0; j < PAD; ++j) {   // l = 2039+j -> win[8+j]
            float2 x = win[8 + j];
            out[cbase + (size_t)(c + 0) * PAD + j] = x.x;
            out[cbase + (size_t)(c + 1) * PAD + j] = x.y;
        }
    }
}

// ---------------------------------------------------------------------------
// launch
// ---------------------------------------------------------------------------
extern "C" void kernel_launch(void* const* d_in, const int* in_sizes, int n_in,
                              void* d_out, int out_size)
{
    const float* hid   = (const float*)d_in[0];
    const int*   ids   = (const int*)  d_in[1];
    const float* table = (const float*)d_in[2];
    const float* Wk    = (const float*)d_in[3];
    const float* bk    = (const float*)d_in[4];
    const float* Wv    = (const float*)d_in[5];
    const float* bv    = (const float*)d_in[6];
    const float* n1    = (const float*)d_in[7];
    const float* n2    = (const float*)d_in[8];
    const float* cw    = (const float*)d_in[9];
    const float* scw   = (const float*)d_in[10];
    float* out = (float*)d_out;

    cudaFuncSetAttribute(gemm_fused, cudaFuncAttributeMaxDynamicSharedMemorySize,
                         SMEM_TOTAL);

    prep<<<ROWS + CONVW_BLOCKS, 256>>>(ids, table, Wk, Wv);
    gemm_fused<<<dim3(NTOT / TILE_N, ROWS / TILE_M), 256, SMEM_TOTAL>>>(
        bk, bv, hid, n1, n2);
    rowstats<<<ROWS / 256, 256>>>();
    int conv_threads = 2048 * B_SZ * NCHUNK;   // 2048 * 1024
    conv_out<<<conv_threads / 256, 256>>>(cw, scw, out);
}

// round 16
// speedup vs baseline: 1.0309x; 1.0290x over previous
#include <cuda_runtime.h>
#include <cuda_fp16.h>
#include <math.h>
#include <stdint.h>

// ---------------------------------------------------------------------------
// Problem constants
// ---------------------------------------------------------------------------
#define B_SZ 4
#define L_SZ 2048
#define G_SZ 2
#define D_SZ 2048
#define H_SZ 16
#define DE_SZ 64
#define E_SZ 1024
#define N_SZ 32768
#define ROWS (B_SZ * L_SZ)  // 8192
#define CD (G_SZ * D_SZ)    // 4096
#define NTOT 6144
#define PAD 9
#define OUT_ELEMS ((size_t)ROWS * CD)
#define EPS_DEF 1.1920928955078125e-7f
#define EPS_SC 1e-5f

#define TILE_M 128
#define TILE_N 128
#define BK 32
#define NITER (E_SZ / BK)      // 32
#define STAGE_BYTES 16384      // A 8K | W 8K
#define NSTAGE 4
#define SMEM_TOTAL (NSTAGE * STAGE_BYTES) // 65536
#define NBLK_K 32
#define NBLK_V 16
#define CONVW_BLOCKS ((NTOT * E_SZ / 4) / 256) // 6144

#define LCH 12                 // rows per conv thread
#define NCHUNK 171             // ceil(2048/12); last chunk over-reads padded rows

// ---------------------------------------------------------------------------
// Scratch (g_vpb/g_rs padded 16 rows so the last conv chunk can over-read)
// ---------------------------------------------------------------------------
__device__ __half g_ea[(size_t)ROWS * E_SZ];
__device__ __half g_wh[(size_t)NTOT * E_SZ];
__device__ float  g_vpb[(size_t)(ROWS + 16) * D_SZ];
__device__ float  g_partK[3 * NBLK_K * (size_t)ROWS]; // [m][blk][row]
__device__ float  g_partV[NBLK_V * (size_t)ROWS];     // [blk][row]
__device__ float4 g_rs[ROWS + 16];                    // {gate0, gate1, q0, q1}

// ---------------------------------------------------------------------------
// PTX helpers
// ---------------------------------------------------------------------------
__device__ __forceinline__ uint32_t smem_to_u32(const void* p) {
    uint32_t a;
    asm("{ .reg .u64 t; cvta.to.shared.u64 t, %1; cvt.u32.u64 %0, t; }"
        : "=r"(a) : "l"(p));
    return a;
}
__device__ __forceinline__ void cpasync16(uint32_t s, const void* g) {
    asm volatile("cp.async.cg.shared.global [%0], [%1], 16;" :: "r"(s), "l"(g));
}
#define CP_COMMIT() asm volatile("cp.async.commit_group;" ::: "memory")
#define CP_WAIT(n)  asm volatile("cp.async.wait_group %0;" :: "n"(n) : "memory")

__device__ __forceinline__ void ldsm4(uint32_t* r, uint32_t a) {
    asm volatile("ldmatrix.sync.aligned.m8n8.x4.shared.b16 {%0,%1,%2,%3}, [%4];"
        : "=r"(r[0]), "=r"(r[1]), "=r"(r[2]), "=r"(r[3]) : "r"(a));
}
__device__ __forceinline__ void mma16816(float* c, const uint32_t* a, const uint32_t* b) {
    asm volatile(
        "mma.sync.aligned.m16n8k16.row.col.f32.f16.f16.f32 "
        "{%0,%1,%2,%3}, {%4,%5,%6,%7}, {%8,%9}, {%0,%1,%2,%3};"
        : "+f"(c[0]), "+f"(c[1]), "+f"(c[2]), "+f"(c[3])
        : "r"(a[0]), "r"(a[1]), "r"(a[2]), "r"(a[3]), "r"(b[0]), "r"(b[1]));
}
__device__ __forceinline__ uint32_t sw32(uint32_t o) { return o ^ ((o >> 3) & 0x10); }

__device__ __forceinline__ float silu_fast(float a) {
    return __fdividef(a, 1.f + __expf(-a));
}

// ---------------------------------------------------------------------------
// 1) prep: gather emb->fp16 + convert W->fp16
// ---------------------------------------------------------------------------
__global__ void __launch_bounds__(256) prep(
    const int* __restrict__ ids, const float* __restrict__ table,
    const float* __restrict__ Wk, const float* __restrict__ Wv)
{
    int blk = blockIdx.x;
    int t = threadIdx.x;
    if (blk < ROWS) {
        int r = blk;
        const int* idr = ids + r * H_SZ;
        int e  = t * 4;
        int h  = e >> 6;
        int de = e & 63;
        int id = idr[h];
        float4 v = *(const float4*)&table[((size_t)(h * N_SZ + id)) * DE_SZ + de];
        __half2 p0, p1;
        p0.x = __float2half_rn(v.x); p0.y = __float2half_rn(v.y);
        p1.x = __float2half_rn(v.z); p1.y = __float2half_rn(v.w);
        *(__half2*)&g_ea[(size_t)r * E_SZ + e]     = p0;
        *(__half2*)&g_ea[(size_t)r * E_SZ + e + 2] = p1;
    } else {
        size_t idx = ((size_t)(blk - ROWS) * 256 + t) * 4;
        size_t n = idx >> 10;
        const float* src = (n < 4096) ? (Wk + idx)
                                      : (Wv + (idx - (size_t)4096 * E_SZ));
        float4 v = *(const float4*)src;
        __half2 h0, h1;
        h0.x = __float2half_rn(v.x); h0.y = __float2half_rn(v.y);
        h1.x = __float2half_rn(v.z); h1.y = __float2half_rn(v.w);
        *(__half2*)&g_wh[idx]     = h0;
        *(__half2*)&g_wh[idx + 2] = h1;
    }
}

// ---------------------------------------------------------------------------
// 2) Merged fp16 GEMM, 128x128 tiles, 2 CTAs/SM (per-tile grid)
// ---------------------------------------------------------------------------
__global__ void __launch_bounds__(256, 2) gemm_fused(
    const float* __restrict__ bk, const float* __restrict__ bv,
    const float* __restrict__ hid,
    const float* __restrict__ n1w, const float* __restrict__ n2w)
{
    extern __shared__ __align__(1024) char smem[];
    const uint32_t sbase = smem_to_u32(smem);
    const int tid = threadIdx.x, wid = tid >> 5, lane = tid & 31;
    const int bx = blockIdx.x;
    const int m0 = blockIdx.y * TILE_M;
    const int n0w = bx * TILE_N;
    const int wm = wid & 1, wn = wid >> 1;

    auto fill = [&](int kt, int s) {
        const uint32_t st = sbase + (uint32_t)s * STAGE_BYTES;
        const int kb = kt * BK;
#pragma unroll
        for (int i = 0; i < 4; ++i) {
            int u = tid + i * 256;
            int isW = (u >= 512);
            int v = u & 511;
            int r = v >> 2, q = v & 3;
            uint32_t a = st + isW * 8192 + (q >> 1) * 4096 +
                         sw32((uint32_t)(r * 32 + (q & 1) * 16));
            const __half* gp = isW ? (g_wh + (size_t)(n0w + r) * E_SZ + kb + q * 8)
                                   : (g_ea + (size_t)(m0 + r) * E_SZ + kb + q * 8);
            cpasync16(a, gp);
        }
    };

    float acc[4][4][4];
#pragma unroll
    for (int mi = 0; mi < 4; ++mi)
#pragma unroll
        for (int ni = 0; ni < 4; ++ni)
#pragma unroll
            for (int j = 0; j < 4; ++j) acc[mi][ni][j] = 0.f;

    fill(0, 0); CP_COMMIT();
    fill(1, 1); CP_COMMIT();
    fill(2, 2); CP_COMMIT();

    const uint32_t offA = sw32((uint32_t)((wm * 64 + (lane & 15)) * 32 + (lane >> 4) * 16));
    const uint32_t offB = sw32((uint32_t)((wn * 32 + ((lane >> 4) << 3) + (lane & 7)) * 32 +
                                          ((lane >> 3) & 1) * 16));

    for (int it = 0; it < NITER; ++it) {
        CP_WAIT(2);
        __syncthreads();
        if (it + 3 < NITER) fill(it + 3, (it + 3) % NSTAGE);
        CP_COMMIT();   // unconditional: keeps wait_group(2) == stage resident

        const uint32_t st = sbase + (uint32_t)(it % NSTAGE) * STAGE_BYTES;
#pragma unroll
        for (int ch = 0; ch < 2; ++ch) {
            const uint32_t aA = st + ch * 4096 + offA;
            const uint32_t bW = st + 8192 + ch * 4096 + offB;
            uint32_t av[4][4], bw[4][2];
#pragma unroll
            for (int mi = 0; mi < 4; ++mi)
                ldsm4(av[mi], aA + (uint32_t)(mi * 16 * 32));
#pragma unroll
            for (int np = 0; np < 2; ++np) {
                uint32_t r4[4];
                ldsm4(r4, bW + (uint32_t)(np * 16 * 32));
                bw[2 * np][0] = r4[0]; bw[2 * np][1] = r4[1];
                bw[2 * np + 1][0] = r4[2]; bw[2 * np + 1][1] = r4[3];
            }
#pragma unroll
            for (int mi = 0; mi < 4; ++mi)
#pragma unroll
                for (int ni = 0; ni < 4; ++ni)
                    mma16816(acc[mi][ni], av[mi], bw[ni]);
        }
        __syncthreads();
    }

    const int gq = lane >> 2, tg = lane & 3;

    if (bx < NBLK_K) {
        const int n0 = bx * TILE_N;
        float* w12s = (float*)smem;
        float* bks  = (float*)(smem) + 128;
        float* sred = (float*)(smem) + 256;
        if (tid < 128) {
            w12s[tid] = n1w[n0 + tid] * n2w[n0 + tid];
            bks[tid]  = bk[n0 + tid];
        }
        __syncthreads();

        float pssk[8], pcr[8], pssq[8];
#pragma unroll
        for (int i = 0; i < 8; ++i) { pssk[i] = 0.f; pcr[i] = 0.f; pssq[i] = 0.f; }

#pragma unroll
        for (int mi = 0; mi < 4; ++mi) {
#pragma unroll
            for (int half = 0; half < 2; ++half) {
                int row = m0 + wm * 64 + mi * 16 + gq + half * 8;
                const float* hrow = hid + (size_t)row * CD + n0;
                int s8 = mi * 2 + half;
#pragma unroll
                for (int ni = 0; ni < 4; ++ni) {
                    int cl = wn * 32 + ni * 8 + tg * 2;
                    float2 h = *(const float2*)&hrow[cl];
                    float k0 = acc[mi][ni][half * 2 + 0] + bks[cl];
                    float k1 = acc[mi][ni][half * 2 + 1] + bks[cl + 1];
                    pssk[s8] += k0 * k0 + k1 * k1;
                    pcr[s8]  += k0 * h.x * w12s[cl] + k1 * h.y * w12s[cl + 1];
                    pssq[s8] += h.x * h.x + h.y * h.y;
                }
            }
        }
#pragma unroll
        for (int i = 0; i < 8; ++i) {
            pssk[i] += __shfl_xor_sync(0xffffffffu, pssk[i], 1);
            pssk[i] += __shfl_xor_sync(0xffffffffu, pssk[i], 2);
            pcr[i]  += __shfl_xor_sync(0xffffffffu, pcr[i], 1);
            pcr[i]  += __shfl_xor_sync(0xffffffffu, pcr[i], 2);
            pssq[i] += __shfl_xor_sync(0xffffffffu, pssq[i], 1);
            pssq[i] += __shfl_xor_sync(0xffffffffu, pssq[i], 2);
        }
        if (tg == 0) {
#pragma unroll
            for (int mi = 0; mi < 4; ++mi)
#pragma unroll
                for (int half = 0; half < 2; ++half) {
                    int rl = wm * 64 + mi * 16 + gq + half * 8;
                    int s8 = mi * 2 + half;
                    sred[0 * 512 + rl * 4 + wn] = pssk[s8];
                    sred[1 * 512 + rl * 4 + wn] = pcr[s8];
                    sred[2 * 512 + rl * 4 + wn] = pssq[s8];
                }
        }
        __syncthreads();
        if (tid < 128) {
#pragma unroll
            for (int m = 0; m < 3; ++m) {
                float s = sred[m * 512 + tid * 4 + 0] + sred[m * 512 + tid * 4 + 1] +
                          sred[m * 512 + tid * 4 + 2] + sred[m * 512 + tid * 4 + 3];
                g_partK[((size_t)m * NBLK_K + bx) * ROWS + m0 + tid] = s;
            }
        }
    } else {
        const int c0 = (bx - NBLK_K) * TILE_N;
        float* bvs  = (float*)smem;
        float* sred = (float*)(smem) + 128;
        if (tid < 128) bvs[tid] = bv[c0 + tid];
        __syncthreads();

        float psv[8];
#pragma unroll
        for (int i = 0; i < 8; ++i) psv[i] = 0.f;

#pragma unroll
        for (int mi = 0; mi < 4; ++mi) {
#pragma unroll
            for (int half = 0; half < 2; ++half) {
                int row = m0 + wm * 64 + mi * 16 + gq + half * 8;
                int s8 = mi * 2 + half;
                float* vrow = g_vpb + (size_t)row * D_SZ + c0;
#pragma unroll
                for (int ni = 0; ni < 4; ++ni) {
                    int cl = wn * 32 + ni * 8 + tg * 2;
                    float v0 = acc[mi][ni][half * 2 + 0] + bvs[cl];
                    float v1 = acc[mi][ni][half * 2 + 1] + bvs[cl + 1];
                    psv[s8] += v0 * v0 + v1 * v1;
                    float2 o; o.x = v0; o.y = v1;
                    *(float2*)&vrow[cl] = o;
                }
            }
        }
#pragma unroll
        for (int i = 0; i < 8; ++i) {
            psv[i] += __shfl_xor_sync(0xffffffffu, psv[i], 1);
            psv[i] += __shfl_xor_sync(0xffffffffu, psv[i], 2);
        }
        if (tg == 0) {
#pragma unroll
            for (int mi = 0; mi < 4; ++mi)
#pragma unroll
                for (int half = 0; half < 2; ++half) {
                    int rl = wm * 64 + mi * 16 + gq + half * 8;
                    sred[rl * 4 + wn] = psv[mi * 2 + half];
                }
        }
        __syncthreads();
        if (tid < 128) {
            float s = sred[tid * 4 + 0] + sred[tid * 4 + 1] +
                      sred[tid * 4 + 2] + sred[tid * 4 + 3];
            g_partV[(size_t)(bx - NBLK_K) * ROWS + m0 + tid] = s;
        }
    }
}

// ---------------------------------------------------------------------------
// 3) rowstats
// ---------------------------------------------------------------------------
__global__ void __launch_bounds__(256) rowstats()
{
    int r = blockIdx.x * 256 + threadIdx.x;
    float ssk[2] = {0.f, 0.f}, cr[2] = {0.f, 0.f}, ssq[2] = {0.f, 0.f};
#pragma unroll
    for (int bx = 0; bx < NBLK_K; ++bx) {
        int gg = bx >> 4;
        ssk[gg] += g_partK[((size_t)0 * NBLK_K + bx) * ROWS + r];
        cr[gg]  += g_partK[((size_t)1 * NBLK_K + bx) * ROWS + r];
        ssq[gg] += g_partK[((size_t)2 * NBLK_K + bx) * ROWS + r];
    }
    float sv = 0.f;
#pragma unroll
    for (int bx = 0; bx < NBLK_V; ++bx)
        sv += g_partV[(size_t)bx * ROWS + r];

    const float invD = 1.0f / 2048.0f;
    const float invSqrtD = 0.022097086912079610f;
    float4 rs;
    float gate[2], q[2];
#pragma unroll
    for (int gg = 0; gg < 2; ++gg) {
        float rsk = rsqrtf(ssk[gg] * invD + EPS_DEF);
        float rsq = rsqrtf(ssq[gg] * invD + EPS_DEF);
        float gt  = rsk * rsq * cr[gg] * invSqrtD;
        float sg  = (gt > 0.f) ? 1.f : ((gt < 0.f) ? -1.f : 0.f);
        float sq  = sqrtf(fmaxf(fabsf(gt), 1e-6f)) * sg;
        gate[gg] = __fdividef(1.f, 1.f + __expf(-sq));
        float inv = rsqrtf(gate[gg] * gate[gg] * sv * invD + EPS_SC);
        q[gg] = gate[gg] * inv;
    }
    rs.x = gate[0]; rs.y = gate[1]; rs.z = q[0]; rs.w = q[1];
    g_rs[r] = rs;
}

// ---------------------------------------------------------------------------
// 4) conv_out: 12 rows/thread, 2 channels, fully static modulo window.
//    Slot = l mod 12 (l0 ≡ 0 mod 12): preload rows l0-9..l0-1 -> slots 3..11,
//    cur row l0+i -> slot i. Taps: l-3 -> (i+9)%12, l-6 -> (i+6)%12,
//    l-9 -> (i+3)%12. Last chunk (l0=2040) over-reads padded rows; stores
//    predicated on l < 2048.
// ---------------------------------------------------------------------------
__global__ void __launch_bounds__(256) conv_out(
    const float* __restrict__ cw, const float* __restrict__ scw,
    float* __restrict__ out)
{
    int t = blockIdx.x * blockDim.x + threadIdx.x;
    int c2 = t & 2047;            // CD/2 groups
    int chunk = t >> 11;          // 0 .. 683
    int b = chunk / NCHUNK;
    int l0 = (chunk - b * NCHUNK) * LCH;

    int c = c2 << 1;
    int gg = c >> 11;
    int d  = c & (D_SZ - 1);
    int r0 = b * L_SZ + l0;

    float4 w0 = *(const float4*)(cw + (size_t)c * 4);
    float4 w1 = *(const float4*)(cw + (size_t)(c + 1) * 4);
    float2 sc = *(const float2*)(scw + c);

    float2 win[LCH];
    if (l0 != 0) {                      // l0 >= 12 > 9: all preload rows valid
        const float* pv = g_vpb + (size_t)(r0 - 9) * D_SZ + d;
        const float4* pr = g_rs + (r0 - 9);
#pragma unroll
        for (int j = 0; j < 9; ++j) {   // row l0-9+j -> slot 3+j
            float2 vv = *(const float2*)pv;
            float4 rr = *pr;
            float q = gg ? rr.w : rr.z;
            float2 x;
            x.x = vv.x * q * sc.x; x.y = vv.y * q * sc.y;
            win[3 + j] = x;
            pv += D_SZ; ++pr;
        }
    } else {
#pragma unroll
        for (int j = 0; j < 9; ++j)
            win[3 + j] = make_float2(0.f, 0.f);
    }

    const float* vp = g_vpb + (size_t)r0 * D_SZ + d;
    const float4* rp = g_rs + r0;
    float* op = out + (size_t)r0 * CD + c;
    const bool full = (l0 != L_SZ - 2 * LCH - 4 + 0) ? true : true; // placeholder opt-out
    (void)full;

#pragma unroll
    for (int i = 0; i < LCH; ++i) {
        int l = l0 + i;
        float2 vo = *(const float2*)vp;
        float4 rr = *rp;
        float gate = gg ? rr.y : rr.x;
        float q    = gg ? rr.w : rr.z;
        float2 x;
        x.x = vo.x * q * sc.x; x.y = vo.y * q * sc.y;
        win[i] = x;

        float a0 = w0.w * x.x, a1 = w1.w * x.y;
        float2 t3 = win[(i + 9) % LCH];   // l-3
        a0 += w0.z * t3.x; a1 += w1.z * t3.y;
        float2 t6 = win[(i + 6) % LCH];   // l-6
        a0 += w0.y * t6.x; a1 += w1.y * t6.y;
        float2 t9 = win[(i + 3) % LCH];   // l-9
        a0 += w0.x * t9.x; a1 += w1.x * t9.y;

        if (l < L_SZ) {
            float2 o;
            o.x = gate * vo.x + silu_fast(a0);
            o.y = gate * vo.y + silu_fast(a1);
            *(float2*)op = o;

            if (l >= L_SZ - PAD) {
                int j = l - (L_SZ - PAD);
                size_t cbase = OUT_ELEMS + (size_t)b * CD * PAD;
                out[cbase + (size_t)(c + 0) * PAD + j] = x.x;
                out[cbase + (size_t)(c + 1) * PAD + j] = x.y;
            }
        }
        vp += D_SZ; ++rp; op += CD;
    }
}

// ---------------------------------------------------------------------------
// launch
// ---------------------------------------------------------------------------
extern "C" void kernel_launch(void* const* d_in, const int* in_sizes, int n_in,
                              void* d_out, int out_size)
{
    const float* hid   = (const float*)d_in[0];
    const int*   ids   = (const int*)  d_in[1];
    const float* table = (const float*)d_in[2];
    const float* Wk    = (const float*)d_in[3];
    const float* bk    = (const float*)d_in[4];
    const float* Wv    = (const float*)d_in[5];
    const float* bv    = (const float*)d_in[6];
    const float* n1    = (const float*)d_in[7];
    const float* n2    = (const float*)d_in[8];
    const float* cw    = (const float*)d_in[9];
    const float* scw   = (const float*)d_in[10];
    float* out = (float*)d_out;

    cudaFuncSetAttribute(gemm_fused, cudaFuncAttributeMaxDynamicSharedMemorySize,
                         SMEM_TOTAL);

    prep<<<ROWS + CONVW_BLOCKS, 256>>>(ids, table, Wk, Wv);
    gemm_fused<<<dim3(NTOT / TILE_N, ROWS / TILE_M), 256, SMEM_TOTAL>>>(
        bk, bv, hid, n1, n2);
    rowstats<<<ROWS / 256, 256>>>();
    int conv_threads = 2048 * B_SZ * NCHUNK;   // 2048 * 684
    conv_out<<<conv_threads / 256, 256>>>(cw, scw, out);
}